// round 2
// baseline (speedup 1.0000x reference)
#include <cuda_runtime.h>
#include <cuda_bf16.h>

// Problem constants (fixed shapes from reference):
// preds:   (16, 19, 512, 512) float32  = 79,691,776 elems
// targets: (16, 1024, 1024)   labels in [0,19)  (harness delivers as int32)
// grid_size = 16 -> cells 32x32 per batch, 16x16 px each

#define N_ELEMS   79691776
#define N4        (N_ELEMS / 4)          // 19,922,944 float4s
#define N_CELLS   16384                  // 16 * 32 * 32
#define LOSS_BLOCKS 2048
#define LOSS_THREADS 256

__device__ unsigned g_masks[N_CELLS];
__device__ double   g_partial[LOSS_BLOCKS];

// ---------------------------------------------------------------------------
// Kernel 1: per-cell class-presence bitmask.
// Nearest-neighbor downsample 1024->512 is stride-2 sampling.
// One warp per cell: 256 sampled labels, OR-reduce bits across the warp.
// Targets indexed as int32 (harness converts int64 inputs to int32).
// ---------------------------------------------------------------------------
__global__ void __launch_bounds__(256) k_presence(const int* __restrict__ t) {
    int warp = (blockIdx.x * blockDim.x + threadIdx.x) >> 5;   // 0..16383
    int lane = threadIdx.x & 31;
    int b    = warp >> 10;          // batch
    int cell = warp & 1023;
    int ch   = cell >> 5;           // cell row 0..31
    int cw   = cell & 31;           // cell col 0..31

    int base = (b << 20);           // element offset of batch (1024*1024 per batch)
    unsigned m = 0;
#pragma unroll
    for (int k = 0; k < 8; ++k) {
        int e = lane + (k << 5);            // 0..255 within cell
        int i = e >> 4;                     // row in cell
        int j = e & 15;                     // col in cell
        // target element: [b, 2*(ch*16+i), 2*(cw*16+j)]
        int off = base + (((ch << 4) + i) << 11) + (((cw << 4) + j) << 1);
        int label = __ldg(&t[off]) & 31;
        m |= 1u << label;
    }
    m = __reduce_or_sync(0xFFFFFFFFu, m);
    if (lane == 0) g_masks[warp] = m;
}

// ---------------------------------------------------------------------------
// MUFU-free softplus: softplus(x) = max(x,0) + ln(1 + e^{-|x|})
//   e^{-|x|}: base-2 split via round-to-nearest magic + deg-4 poly for 2^r
//   ln(1+y), y in (0,1]: deg-6 poly in xx = 2y-1 (Chebyshev-derived,
//   truncation error ~1.5e-6)
// ---------------------------------------------------------------------------
__device__ __forceinline__ float softplus_fast(float x) {
    float z  = fabsf(x) * -1.4426950408889634f;   // -|x| * log2(e)
    float mm = z + 12582912.0f;                   // round(z) via RN magic (1.5*2^23)
    float rz = mm - 12582912.0f;
    float r  = z - rz;                            // r in [-0.5, 0.5]
    int   im = __float_as_int(mm);
    // exponent scale 2^round(z):  (127 + rz) << 23, wraps correctly mod 2^32
    float scale = __int_as_float(im * 8388608 + 0x3F800000);
    // 2^r, deg-4
    float p = 0.00961812911f;
    p = fmaf(p, r, 0.05550410866f);
    p = fmaf(p, r, 0.24022650696f);
    p = fmaf(p, r, 0.69314718056f);
    p = fmaf(p, r, 1.0f);
    float y  = scale * p;                         // = e^{-|x|} in (0, 1]
    float xx = fmaf(2.0f, y, -1.0f);              // in (-1, 1]
    float q = -0.0002721f;
    q = fmaf(q, xx,  0.0009516f);
    q = fmaf(q, xx, -0.0030580f);
    q = fmaf(q, xx,  0.0122789f);
    q = fmaf(q, xx, -0.0555614f);
    q = fmaf(q, xx,  0.3333419f);
    q = fmaf(q, xx,  0.4054654f);                 // ln(1+y)
    return fmaxf(x, 0.0f) + q;
}

// ---------------------------------------------------------------------------
// Kernel 2: streaming loss reduction over preds (float4 grid-stride).
// Each float4 lies entirely inside one 16-px cell, so one mask fetch
// (64 KB table -> L1/L2-resident) serves 4 elements.
// Per-block deterministic double partial.
// ---------------------------------------------------------------------------
__global__ void __launch_bounds__(LOSS_THREADS) k_loss(const float4* __restrict__ p4) {
    int stride = gridDim.x * blockDim.x;
    double acc = 0.0;
    for (int idx = blockIdx.x * blockDim.x + threadIdx.x; idx < N4; idx += stride) {
        float4 v = p4[idx];
        int lin = idx << 2;                 // linear element index
        int w   = lin & 511;
        int hw  = lin >> 9;
        int h   = hw & 511;
        int bc  = hw >> 9;                  // b*19 + c, < 304
        int b   = bc / 19;                  // const-div -> mulhi
        int c   = bc - b * 19;
        unsigned mask = g_masks[(b << 10) + ((h >> 4) << 5) + (w >> 4)];
        float sef = (float)((mask >> c) & 1u);
        float s = ((softplus_fast(v.x) + softplus_fast(v.y)) +
                   (softplus_fast(v.z) + softplus_fast(v.w)));
        float dot = (v.x + v.y) + (v.z + v.w);
        acc += (double)fmaf(-sef, dot, s);  // sum of softplus(x_i) - se*x_i
    }
    // block reduction (deterministic)
    __shared__ double smem[LOSS_THREADS / 32];
    for (int o = 16; o > 0; o >>= 1) acc += __shfl_down_sync(0xFFFFFFFFu, acc, o);
    if ((threadIdx.x & 31) == 0) smem[threadIdx.x >> 5] = acc;
    __syncthreads();
    if (threadIdx.x < (LOSS_THREADS / 32)) {
        double a = smem[threadIdx.x];
        for (int o = (LOSS_THREADS / 64); o > 0; o >>= 1)
            a += __shfl_down_sync(0xFFu, a, o);
        if (threadIdx.x == 0) g_partial[blockIdx.x] = a;
    }
}

// ---------------------------------------------------------------------------
// Kernel 3: final deterministic reduction of block partials -> mean.
// ---------------------------------------------------------------------------
__global__ void __launch_bounds__(256) k_final(float* __restrict__ out) {
    __shared__ double smem[8];
    double a = 0.0;
    for (int i = threadIdx.x; i < LOSS_BLOCKS; i += 256) a += g_partial[i];
    for (int o = 16; o > 0; o >>= 1) a += __shfl_down_sync(0xFFFFFFFFu, a, o);
    if ((threadIdx.x & 31) == 0) smem[threadIdx.x >> 5] = a;
    __syncthreads();
    if (threadIdx.x < 8) {
        double v = smem[threadIdx.x];
        for (int o = 4; o > 0; o >>= 1) v += __shfl_down_sync(0xFFu, v, o);
        if (threadIdx.x == 0) out[0] = (float)(v * (1.0 / (double)N_ELEMS));
    }
}

extern "C" void kernel_launch(void* const* d_in, const int* in_sizes, int n_in,
                              void* d_out, int out_size) {
    const float* preds   = (const float*)d_in[0];
    const int*   targets = (const int*)d_in[1];
    float*       out     = (float*)d_out;

    k_presence<<<N_CELLS / 8, 256>>>(targets);
    k_loss<<<LOSS_BLOCKS, LOSS_THREADS>>>((const float4*)preds);
    k_final<<<1, 256>>>(out);
}

// round 3
// speedup vs baseline: 1.1001x; 1.1001x over previous
#include <cuda_runtime.h>
#include <cuda_bf16.h>

// Problem constants (fixed shapes):
// preds:   (16, 19, 512, 512) float32  = 79,691,776 elems
// targets: (16, 1024, 1024)   labels in [0,19) (delivered as int32)
// grid_size = 16 -> 32x32 cells per batch, 16x16 px each

#define N_ELEMS   79691776
#define N4        (N_ELEMS / 4)          // 19,922,944 float4s
#define N_CELLS   16384                  // 16 * 32 * 32
#define LOSS_BLOCKS  2048
#define LOSS_THREADS 256
#define LOSS_STRIDE  (LOSS_BLOCKS * LOSS_THREADS)   // 524288; N4/STRIDE = 38 exactly
#define LOSS_ITERS   38

__device__ unsigned g_masks[N_CELLS];
__device__ double   g_partial[LOSS_BLOCKS];

// ---------------------------------------------------------------------------
// Kernel 1: per-cell class-presence bitmask.
// NN-downsample 1024->512 = stride-2 sampling. int4 loads: each 16B load
// yields 2 sampled labels (.x, .z). 4 loads/lane, one warp per cell.
// ---------------------------------------------------------------------------
__global__ void __launch_bounds__(256) k_presence(const int4* __restrict__ t4) {
    int warp = (blockIdx.x * blockDim.x + threadIdx.x) >> 5;   // 0..16383
    int lane = threadIdx.x & 31;
    int b    = warp >> 10;
    int cell = warp & 1023;
    int ch   = cell >> 5;
    int cw   = cell & 31;

    int base4 = b << 18;                    // 1024*1024/4 int4s per batch
    unsigned m = 0;
#pragma unroll
    for (int k = 0; k < 4; ++k) {
        int e  = lane + (k << 5);           // 0..127 : 16 rows x 8 int4/row
        int i  = e >> 3;                    // row in cell
        int jj = e & 7;                     // int4 within sampled row span
        // orig row = 2*(ch*16+i); int4 row stride = 512
        int off = base4 + (((ch << 4) + i) << 9) + (cw << 3) + jj;
        int4 q = __ldg(&t4[off]);
        m |= (1u << (q.x & 31)) | (1u << (q.z & 31));
    }
    m = __reduce_or_sync(0xFFFFFFFFu, m);
    if (lane == 0) g_masks[warp] = m;
}

// ---------------------------------------------------------------------------
// MUFU softplus core: softplus(y) = max(y,0) + ln2 * lg2(1 + ex2(-|y|*log2e))
// ex2 input <= 0, lg2 input in [1,2] (well-conditioned). 2 MUFU + 3 fma ops.
// BCE identity: softplus(x) - se*x = softplus(se ? -x : x), and |y|=|x| so
// the se-flip is a single sign-bit XOR feeding only the max() term.
// ---------------------------------------------------------------------------
__device__ __forceinline__ float ex2_(float x) { float r; asm("ex2.approx.f32 %0, %1;" : "=f"(r) : "f"(x)); return r; }
__device__ __forceinline__ float lg2_(float x) { float r; asm("lg2.approx.f32 %0, %1;" : "=f"(r) : "f"(x)); return r; }

__device__ __forceinline__ float bce_elem(float x, unsigned sgn) {
    float t = ex2_(fabsf(x) * -1.4426950408889634f);       // e^{-|x|} in (0,1]
    float l = lg2_(1.0f + t);                              // log2(1+t)
    float y = __int_as_float(__float_as_int(x) ^ sgn);     // se ? -x : x
    return fmaf(l, 0.6931471805599453f, fmaxf(y, 0.0f));
}

// ---------------------------------------------------------------------------
// Kernel 2: streaming loss reduction over preds.
// Exact 38-iteration loop; h,w (and hence the cell column/row part of the
// mask index) are loop-invariant per thread; only bc = bc0 + 8k varies.
// ---------------------------------------------------------------------------
__global__ void __launch_bounds__(LOSS_THREADS) k_loss(const float4* __restrict__ p4) {
    int tid = blockIdx.x * blockDim.x + threadIdx.x;
    int lin = tid << 2;                     // element index of iter 0
    int w   = lin & 511;
    int h   = (lin >> 9) & 511;
    int cellhw = ((h >> 4) << 5) + (w >> 4);   // loop-invariant
    int bc0 = lin >> 18;                       // b*19+c at iter 0; +8 per iter

    double acc = 0.0;
#pragma unroll 2
    for (int k = 0; k < LOSS_ITERS; ++k) {
        float4 v = __ldcs(p4 + tid + k * LOSS_STRIDE);
        int bc = bc0 + (k << 3);
        int b  = bc / 19;
        int c  = bc - b * 19;
        unsigned mask = g_masks[(b << 10) + cellhw];
        unsigned sgn  = ((mask >> c) & 1u) << 31;
        float s = (bce_elem(v.x, sgn) + bce_elem(v.y, sgn)) +
                  (bce_elem(v.z, sgn) + bce_elem(v.w, sgn));
        acc += (double)s;
    }
    // deterministic block reduction
    __shared__ double smem[LOSS_THREADS / 32];
    for (int o = 16; o > 0; o >>= 1) acc += __shfl_down_sync(0xFFFFFFFFu, acc, o);
    if ((threadIdx.x & 31) == 0) smem[threadIdx.x >> 5] = acc;
    __syncthreads();
    if (threadIdx.x < (LOSS_THREADS / 32)) {
        double a = smem[threadIdx.x];
        for (int o = (LOSS_THREADS / 64); o > 0; o >>= 1)
            a += __shfl_down_sync(0xFFu, a, o);
        if (threadIdx.x == 0) g_partial[blockIdx.x] = a;
    }
}

// ---------------------------------------------------------------------------
// Kernel 3: final deterministic reduction -> mean.
// ---------------------------------------------------------------------------
__global__ void __launch_bounds__(256) k_final(float* __restrict__ out) {
    __shared__ double smem[8];
    double a = 0.0;
    for (int i = threadIdx.x; i < LOSS_BLOCKS; i += 256) a += g_partial[i];
    for (int o = 16; o > 0; o >>= 1) a += __shfl_down_sync(0xFFFFFFFFu, a, o);
    if ((threadIdx.x & 31) == 0) smem[threadIdx.x >> 5] = a;
    __syncthreads();
    if (threadIdx.x < 8) {
        double v = smem[threadIdx.x];
        for (int o = 4; o > 0; o >>= 1) v += __shfl_down_sync(0xFFu, v, o);
        if (threadIdx.x == 0) out[0] = (float)(v * (1.0 / (double)N_ELEMS));
    }
}

extern "C" void kernel_launch(void* const* d_in, const int* in_sizes, int n_in,
                              void* d_out, int out_size) {
    const float* preds   = (const float*)d_in[0];
    const int4*  targets = (const int4*)d_in[1];
    float*       out     = (float*)d_out;

    k_presence<<<N_CELLS / 8, 256>>>(targets);
    k_loss<<<LOSS_BLOCKS, LOSS_THREADS>>>((const float4*)preds);
    k_final<<<1, 256>>>(out);
}

// round 4
// speedup vs baseline: 1.6878x; 1.5342x over previous
#include <cuda_runtime.h>
#include <cuda_bf16.h>

// preds:   (16, 19, 512, 512) float32  = 79,691,776 elems
// targets: (16, 1024, 1024)   labels in [0,19) (delivered as int32)
// grid_size = 16 -> 32x32 cells per batch, 16x16 px each

#define N_ELEMS   79691776
#define N4        (N_ELEMS / 4)          // 19,922,944 float4s
#define N_CELLS   16384
#define LOSS_BLOCKS  2048
#define LOSS_THREADS 256
#define LOSS_STRIDE  (LOSS_BLOCKS * LOSS_THREADS)   // N4/STRIDE = 38 exactly
#define LOSS_ITERS   38

__device__ unsigned g_masks[N_CELLS];
__device__ double   g_partial[LOSS_BLOCKS];

// ---------------------------------------------------------------------------
// Kernel 1: per-cell class-presence bitmask (stride-2 NN downsample).
// ---------------------------------------------------------------------------
__global__ void __launch_bounds__(256) k_presence(const int4* __restrict__ t4) {
    int warp = (blockIdx.x * blockDim.x + threadIdx.x) >> 5;
    int lane = threadIdx.x & 31;
    int b    = warp >> 10;
    int cell = warp & 1023;
    int ch   = cell >> 5;
    int cw   = cell & 31;

    int base4 = b << 18;
    unsigned m = 0;
#pragma unroll
    for (int k = 0; k < 4; ++k) {
        int e  = lane + (k << 5);
        int i  = e >> 3;
        int jj = e & 7;
        int off = base4 + (((ch << 4) + i) << 9) + (cw << 3) + jj;
        int4 q = __ldg(&t4[off]);
        m |= (1u << (q.x & 31)) | (1u << (q.z & 31));
    }
    m = __reduce_or_sync(0xFFFFFFFFu, m);
    if (lane == 0) g_masks[warp] = m;
}

// ---------------------------------------------------------------------------
// BCE element, split accumulation (NO per-iter fp64, NO per-iter horizontal):
//   bce(x) = ln2 * lg2(1 + e^{-|x|})  +  relu(se ? -x : x)
// acc_l collects lg2 terms, acc_a collects relu terms; combine once at end.
// ---------------------------------------------------------------------------
__device__ __forceinline__ float ex2_(float x) { float r; asm("ex2.approx.f32 %0, %1;" : "=f"(r) : "f"(x)); return r; }
__device__ __forceinline__ float lg2_(float x) { float r; asm("lg2.approx.f32 %0, %1;" : "=f"(r) : "f"(x)); return r; }

__device__ __forceinline__ void bce_acc(float x, unsigned sgn, float& al, float& aa) {
    float t = ex2_(fabsf(x) * -1.4426950408889634f);   // e^{-|x|} in (0,1]
    al += lg2_(1.0f + t);                              // log2(1+t) in (0,1]
    float y = __int_as_float(__float_as_int(x) ^ sgn); // se ? -x : x
    aa += fmaxf(y, 0.0f);
}

// ---------------------------------------------------------------------------
// Kernel 2: streaming loss reduction (float4 grid-stride, exact 38 iters).
// ---------------------------------------------------------------------------
__global__ void __launch_bounds__(LOSS_THREADS) k_loss(const float4* __restrict__ p4) {
    int tid = blockIdx.x * blockDim.x + threadIdx.x;
    int lin = tid << 2;
    int w   = lin & 511;
    int h   = (lin >> 9) & 511;
    int cellhw = ((h >> 4) << 5) + (w >> 4);   // loop-invariant
    int bc0 = lin >> 18;                       // b*19+c at iter 0; +8 per iter

    float al0 = 0.f, al1 = 0.f, aa0 = 0.f, aa1 = 0.f;
#pragma unroll 2
    for (int k = 0; k < LOSS_ITERS; ++k) {
        float4 v = __ldcs(p4 + tid + k * LOSS_STRIDE);
        int bc = bc0 + (k << 3);
        int b  = bc / 19;
        int c  = bc - b * 19;
        unsigned mask = g_masks[(b << 10) + cellhw];
        unsigned sgn  = ((mask >> c) & 1u) << 31;
        bce_acc(v.x, sgn, al0, aa0);
        bce_acc(v.y, sgn, al1, aa1);
        bce_acc(v.z, sgn, al0, aa0);
        bce_acc(v.w, sgn, al1, aa1);
    }
    // single fp64 conversion per thread
    double acc = (double)(al0 + al1) * 0.6931471805599453 + (double)(aa0 + aa1);

    // deterministic block reduction
    __shared__ double smem[LOSS_THREADS / 32];
    for (int o = 16; o > 0; o >>= 1) acc += __shfl_down_sync(0xFFFFFFFFu, acc, o);
    if ((threadIdx.x & 31) == 0) smem[threadIdx.x >> 5] = acc;
    __syncthreads();
    if (threadIdx.x < (LOSS_THREADS / 32)) {
        double a = smem[threadIdx.x];
        for (int o = (LOSS_THREADS / 64); o > 0; o >>= 1)
            a += __shfl_down_sync(0xFFu, a, o);
        if (threadIdx.x == 0) g_partial[blockIdx.x] = a;
    }
}

// ---------------------------------------------------------------------------
// Kernel 3: final deterministic reduction -> mean.
// ---------------------------------------------------------------------------
__global__ void __launch_bounds__(256) k_final(float* __restrict__ out) {
    __shared__ double smem[8];
    double a = 0.0;
    for (int i = threadIdx.x; i < LOSS_BLOCKS; i += 256) a += g_partial[i];
    for (int o = 16; o > 0; o >>= 1) a += __shfl_down_sync(0xFFFFFFFFu, a, o);
    if ((threadIdx.x & 31) == 0) smem[threadIdx.x >> 5] = a;
    __syncthreads();
    if (threadIdx.x < 8) {
        double v = smem[threadIdx.x];
        for (int o = 4; o > 0; o >>= 1) v += __shfl_down_sync(0xFFu, v, o);
        if (threadIdx.x == 0) out[0] = (float)(v * (1.0 / (double)N_ELEMS));
    }
}

extern "C" void kernel_launch(void* const* d_in, const int* in_sizes, int n_in,
                              void* d_out, int out_size) {
    const float* preds   = (const float*)d_in[0];
    const int4*  targets = (const int4*)d_in[1];
    float*       out     = (float*)d_out;

    k_presence<<<N_CELLS / 8, 256>>>(targets);
    k_loss<<<LOSS_BLOCKS, LOSS_THREADS>>>((const float4*)preds);
    k_final<<<1, 256>>>(out);
}